// round 15
// baseline (speedup 1.0000x reference)
#include <cuda_runtime.h>
#include <cuda_bf16.h>

#define HD 256
#define BG 64
#define NPGC 4096
#define C0C 256
#define C1C 64
#define NTOT (BG*NPGC)
#define KSPLIT 16

__device__ unsigned g_A0P[(size_t)BG*C0C*NPGC];  // packed bf16 hi|lo<<16, [g][c][n]
__device__ unsigned g_W0H[C0C*HD/2];             // W0^T hi pairs [c][128]
__device__ unsigned g_W0L[C0C*HD/2];
__device__ float g_f0[(size_t)BG*C0C*HD];
__device__ float g_A1[(size_t)BG*C0C*C1C];
__device__ float g_f1[(size_t)BG*C1C*HD];
__device__ float g_part[(size_t)KSPLIT*BG*HD];

__device__ __forceinline__ unsigned pack1(float v){
    __nv_bfloat16 h = __float2bfloat16(v);
    __nv_bfloat16 lo = __float2bfloat16(v - __bfloat162float(h));
    return (unsigned)__bfloat16_as_ushort(h) | ((unsigned)__bfloat16_as_ushort(lo)<<16);
}
__device__ __forceinline__ void split2(float a, float b, unsigned& hi, unsigned& lo){
    __nv_bfloat16 ha = __float2bfloat16(a), hb = __float2bfloat16(b);
    __nv_bfloat16 la = __float2bfloat16(a - __bfloat162float(ha));
    __nv_bfloat16 lb = __float2bfloat16(b - __bfloat162float(hb));
    hi = (unsigned)__bfloat16_as_ushort(ha) | ((unsigned)__bfloat16_as_ushort(hb)<<16);
    lo = (unsigned)__bfloat16_as_ushort(la) | ((unsigned)__bfloat16_as_ushort(lb)<<16);
}
__device__ __forceinline__ void mma16816(float* c, const unsigned* a, const unsigned* b){
    asm volatile("mma.sync.aligned.m16n8k16.row.col.f32.bf16.bf16.f32 "
        "{%0,%1,%2,%3}, {%4,%5,%6,%7}, {%8,%9}, {%0,%1,%2,%3};"
        : "+f"(c[0]),"+f"(c[1]),"+f"(c[2]),"+f"(c[3])
        : "r"(a[0]),"r"(a[1]),"r"(a[2]),"r"(a[3]), "r"(b[0]),"r"(b[1]));
}

// W0^T split into hi/lo pair arrays
__global__ void kW(const float* __restrict__ W0){
    int i = blockIdx.x*256 + threadIdx.x;    // 32768
    int c = i>>7, kp = i&127;
    unsigned hi, lo;
    split2(W0[(size_t)(2*kp)*C0C + c], W0[(size_t)(2*kp+1)*C0C + c], hi, lo);
    g_W0H[c*128+kp] = hi; g_W0L[c*128+kp] = lo;
}

__global__ void kNop(){}   // spacer: ncu captures my idx-3 launch -> k2m

// =========================================================================
// k1m: A0 = softmax(x@W0+b0). Tile M=64 x N=256, 2 CTAs/SM. (unchanged R14)
// u32 off: sums=0[256], b0s=256, sXh=512, sXl=2816, sWh=5120, sWl=14336,
//          end 23552. buf=512 [256][68] (..17920).
// =========================================================================
#define K1_SMEM (23552*4)   // 94208
__global__ __launch_bounds__(256,2) void k1m(const float* __restrict__ x,
                                             const float* __restrict__ b0){
    extern __shared__ __align__(16) unsigned sm[];
    float* sums = (float*)sm;
    float* b0s  = (float*)(sm + 256);
    unsigned* sXh = sm + 512;                 // [64][36]
    unsigned* sXl = sm + 2816;
    unsigned* sWh = sm + 5120;                // [256][36]
    unsigned* sWl = sm + 14336;
    unsigned* buf = sm + 512;                 // epilogue staging [256][68]
    const int tid = threadIdx.x, l = tid&31, wid = tid>>5;
    const int wm = wid&1, wn = wid>>1;
    const int row0 = blockIdx.x*64;

    b0s[tid] = b0[tid];
    float acc[2][8][4];
#pragma unroll
    for(int t=0;t<2;t++)
#pragma unroll
        for(int j=0;j<8;j++)
#pragma unroll
            for(int q=0;q<4;q++) acc[t][j][q]=0.f;

    for(int kc=0;kc<4;kc++){
#pragma unroll
        for(int i=0;i<4;i++){
            int idx = tid + i*256, r = idx>>4, q = idx&15;
            float4 v = *(const float4*)(x + (size_t)(row0+r)*HD + kc*64 + q*4);
            unsigned h0,l0,h1,l1;
            split2(v.x, v.y, h0, l0); split2(v.z, v.w, h1, l1);
            *(uint2*)(sXh + r*36 + q*2) = make_uint2(h0,h1);
            *(uint2*)(sXl + r*36 + q*2) = make_uint2(l0,l1);
        }
#pragma unroll
        for(int i=0;i<8;i++){
            int idx = tid + i*256, c = idx>>3, q = (idx&7)*4;
            *(uint4*)(sWh + c*36 + q) = *(const uint4*)(g_W0H + c*128 + kc*32 + q);
            *(uint4*)(sWl + c*36 + q) = *(const uint4*)(g_W0L + c*128 + kc*32 + q);
        }
        __syncthreads();
        for(int k16=0;k16<4;k16++){
            int kp = k16*8;
            unsigned ah[2][4], al[2][4];
#pragma unroll
            for(int t=0;t<2;t++){
                int ra = (wm*32 + t*16 + (l>>2))*36 + kp + (l&3);
                ah[t][0]=sXh[ra];       ah[t][1]=sXh[ra+8*36];
                ah[t][2]=sXh[ra+4];     ah[t][3]=sXh[ra+8*36+4];
                al[t][0]=sXl[ra];       al[t][1]=sXl[ra+8*36];
                al[t][2]=sXl[ra+4];     al[t][3]=sXl[ra+8*36+4];
            }
#pragma unroll
            for(int j=0;j<8;j++){
                int rb = (wn*64 + j*8 + (l>>2))*36 + kp + (l&3);
                unsigned bh[2], bl[2];
                bh[0]=sWh[rb]; bh[1]=sWh[rb+4];
                bl[0]=sWl[rb]; bl[1]=sWl[rb+4];
#pragma unroll
                for(int t=0;t<2;t++){
                    mma16816(acc[t][j], ah[t], bh);
                    mma16816(acc[t][j], ah[t], bl);
                    mma16816(acc[t][j], al[t], bh);
                }
            }
        }
        __syncthreads();
    }

    float rs[2][2] = {{0.f,0.f},{0.f,0.f}};
#pragma unroll
    for(int t=0;t<2;t++)
#pragma unroll
        for(int j=0;j<8;j++){
            int col = wn*64 + j*8 + (l&3)*2;
            float e0=__expf(acc[t][j][0]+b0s[col]),   e1=__expf(acc[t][j][1]+b0s[col+1]);
            float e2=__expf(acc[t][j][2]+b0s[col]),   e3=__expf(acc[t][j][3]+b0s[col+1]);
            acc[t][j][0]=e0; acc[t][j][1]=e1; acc[t][j][2]=e2; acc[t][j][3]=e3;
            rs[t][0]+=e0+e1; rs[t][1]+=e2+e3;
        }
#pragma unroll
    for(int t=0;t<2;t++)
#pragma unroll
        for(int h=0;h<2;h++){
            float s = rs[t][h];
            s += __shfl_xor_sync(~0u,s,1); s += __shfl_xor_sync(~0u,s,2);
            rs[t][h]=s;
        }
    if((l&3)==0){
#pragma unroll
        for(int t=0;t<2;t++)
#pragma unroll
            for(int h=0;h<2;h++)
                sums[(wm*32+t*16+(l>>2)+8*h)*4 + wn] = rs[t][h];
    }
    __syncthreads();
    float inv[2][2];
#pragma unroll
    for(int t=0;t<2;t++)
#pragma unroll
        for(int h=0;h<2;h++){
            int r = wm*32+t*16+(l>>2)+8*h;
            inv[t][h] = 1.0f/(sums[r*4]+sums[r*4+1]+sums[r*4+2]+sums[r*4+3]);
        }
#pragma unroll
    for(int t=0;t<2;t++)
#pragma unroll
        for(int j=0;j<8;j++){
            int col = wn*64 + j*8 + (l&3)*2;
            int r0 = wm*32 + t*16 + (l>>2), r1 = r0+8;
            buf[col*68 + r0]     = pack1(acc[t][j][0]*inv[t][0]);
            buf[(col+1)*68 + r0] = pack1(acc[t][j][1]*inv[t][0]);
            buf[col*68 + r1]     = pack1(acc[t][j][2]*inv[t][1]);
            buf[(col+1)*68 + r1] = pack1(acc[t][j][3]*inv[t][1]);
        }
    __syncthreads();
    const int g = row0>>12, nl0 = row0&4095;
#pragma unroll
    for(int cc=0;cc<16;cc++){
        int c = wid*32 + cc*2 + (l>>4);
        uint4 v = *(uint4*)(buf + c*68 + (l&15)*4);
        *(uint4*)(g_A0P + ((size_t)g*C0C + c)*NPGC + nl0 + (l&15)*4) = v;
    }
}

// =========================================================================
// k2m: f0 = A0^T @ x. Tile M=128 x N=64, 256 thr (8 warps 4m x 2n),
// SMEM 72704B -> 3 CTAs/SM. grid (4 n, 2 m, 64 g) = 512.
// u32 off: sAh=0 [128][36]=4608, sAl=4608 (..9216), sBh=9216 [64][36]=2304
//          (..11520), sBl=11520 (..13824), sF=13824 [64][68] f32 (..18176).
// =========================================================================
#define K2_SMEM (18176*4)   // 72704
__global__ __launch_bounds__(256,3) void k2m(const float* __restrict__ x){
    extern __shared__ __align__(16) unsigned sm[];
    unsigned* sAh = sm;
    unsigned* sAl = sm + 4608;
    unsigned* sBh = sm + 9216;
    unsigned* sBl = sm + 11520;
    float*    sF  = (float*)(sm + 13824);     // [64 n][68 h]
    const int tid = threadIdx.x, l = tid&31, wid = tid>>5;
    const int wm = wid&3, wn = wid>>2;        // 4 m-warps x 2 n-warps
    const int n0 = blockIdx.x*64, m0 = blockIdx.y*128, g = blockIdx.z;
    const unsigned* Ap = g_A0P + (size_t)g*C0C*NPGC;
    const float* xp = x + (size_t)g*NPGC*HD;

    float acc[2][4][4];
#pragma unroll
    for(int t=0;t<2;t++)
#pragma unroll
        for(int j=0;j<4;j++)
#pragma unroll
            for(int q=0;q<4;q++) acc[t][j][q]=0.f;

    for(int kc=0;kc<64;kc++){
        // A chunk [128 c][64 n] packed -> hi/lo pairs (2048 uint4, 8/thr)
#pragma unroll
        for(int i=0;i<8;i++){
            int idx = tid + i*256, r = idx>>4, q = idx&15;
            uint4 w = *(const uint4*)(Ap + (size_t)(m0+r)*NPGC + kc*64 + q*4);
            unsigned h01 = __byte_perm(w.x,w.y,0x5410), h23 = __byte_perm(w.z,w.w,0x5410);
            unsigned l01 = __byte_perm(w.x,w.y,0x7632), l23 = __byte_perm(w.z,w.w,0x7632);
            *(uint2*)(sAh + r*36 + q*2) = make_uint2(h01,h23);
            *(uint2*)(sAl + r*36 + q*2) = make_uint2(l01,l23);
        }
        // x chunk [64 n][64 h] fp32 (this CTA's h slice; 1024 float4, 4/thr)
#pragma unroll
        for(int i=0;i<4;i++){
            int idx = tid + i*256, n = idx>>4, h4 = idx&15;
            *(float4*)(sF + n*68 + h4*4) =
                *(const float4*)(xp + (size_t)(kc*64+n)*HD + n0 + h4*4);
        }
        __syncthreads();
        // transpose + split: h = tid&63, 4 n-quads per thread
        {
            int h = tid & 63;
            int n4b = (tid >> 6) * 4;
#pragma unroll
            for(int n4=0;n4<4;n4++){
                int nn = n4b + n4;
                float f0v = sF[(nn*4+0)*68 + h], f1v = sF[(nn*4+1)*68 + h];
                float f2v = sF[(nn*4+2)*68 + h], f3v = sF[(nn*4+3)*68 + h];
                unsigned h0,l0,h1,l1;
                split2(f0v, f1v, h0, l0); split2(f2v, f3v, h1, l1);
                *(uint2*)(sBh + h*36 + nn*2) = make_uint2(h0,h1);
                *(uint2*)(sBl + h*36 + nn*2) = make_uint2(l0,l1);
            }
        }
        __syncthreads();
        for(int k16=0;k16<4;k16++){
            int kp = k16*8;
            unsigned ah[2][4], al[2][4];
#pragma unroll
            for(int t=0;t<2;t++){
                int ra = (wm*32 + t*16 + (l>>2))*36 + kp + (l&3);
                ah[t][0]=sAh[ra];       ah[t][1]=sAh[ra+8*36];
                ah[t][2]=sAh[ra+4];     ah[t][3]=sAh[ra+8*36+4];
                al[t][0]=sAl[ra];       al[t][1]=sAl[ra+8*36];
                al[t][2]=sAl[ra+4];     al[t][3]=sAl[ra+8*36+4];
            }
#pragma unroll
            for(int j=0;j<4;j++){
                int rb = (wn*32 + j*8 + (l>>2))*36 + kp + (l&3);
                unsigned bh[2], bl[2];
                bh[0]=sBh[rb]; bh[1]=sBh[rb+4];
                bl[0]=sBl[rb]; bl[1]=sBl[rb+4];
#pragma unroll
                for(int t=0;t<2;t++){
                    mma16816(acc[t][j], ah[t], bh);
                    mma16816(acc[t][j], ah[t], bl);
                    mma16816(acc[t][j], al[t], bh);
                }
            }
        }
        __syncthreads();
    }
    float* f0p = g_f0 + ((size_t)g*C0C + m0)*HD + n0;
#pragma unroll
    for(int t=0;t<2;t++)
#pragma unroll
        for(int j=0;j<4;j++){
            int col = wn*32 + j*8 + (l&3)*2;
            int r0 = wm*32 + t*16 + (l>>2);
            *(float2*)(f0p + (size_t)r0*HD + col)     = make_float2(acc[t][j][0],acc[t][j][1]);
            *(float2*)(f0p + (size_t)(r0+8)*HD + col) = make_float2(acc[t][j][2],acc[t][j][3]);
        }
}

// ---- k3: A1 = softmax(f0 @ W1 + b1). 2 rows per warp, 32 rows/block ----
#define K3_SMEM ((256*64 + 32*256)*4)   // 98304
__global__ __launch_bounds__(512) void k3n(const float* __restrict__ W1,
                                           const float* __restrict__ b1){
    extern __shared__ float s3[];
    float* sW = s3;                // [256][64]
    float* srow = s3 + 16384;      // [32][256]
    const int tid = threadIdx.x, l = tid&31, w = tid>>5;
#pragma unroll
    for(int i=0;i<8;i++){
        int idx = tid + i*512;
        *(float4*)(sW + idx*4) = *(const float4*)(W1 + idx*4);
    }
    const int row0 = blockIdx.x*32 + w*2;
    const float* xr0 = g_f0 + (size_t)row0*HD;
#pragma unroll
    for(int rr=0;rr<2;rr++){
        *(float4*)(srow + (w*2+rr)*256 + l*8)     = *(const float4*)(xr0 + rr*HD + l*8);
        *(float4*)(srow + (w*2+rr)*256 + l*8 + 4) = *(const float4*)(xr0 + rr*HD + l*8 + 4);
    }
    __syncthreads();
    float a00=0.f,a01=0.f,a10=0.f,a11=0.f;
    const float* rw0 = srow + (w*2)*256;
    const float* rw1 = srow + (w*2+1)*256;
#pragma unroll 8
    for(int k=0;k<HD;k++){
        float2 wv = *(float2*)(sW + k*64 + 2*l);
        float x0 = rw0[k], x1 = rw1[k];
        a00 = fmaf(x0, wv.x, a00); a01 = fmaf(x0, wv.y, a01);
        a10 = fmaf(x1, wv.x, a10); a11 = fmaf(x1, wv.y, a11);
    }
    float2 bb = *(const float2*)(b1 + 2*l);
    a00 += bb.x; a01 += bb.y; a10 += bb.x; a11 += bb.y;
    float m0v = fmaxf(a00,a01), m1v = fmaxf(a10,a11);
#pragma unroll
    for (int o=16;o;o>>=1){
        m0v = fmaxf(m0v, __shfl_xor_sync(~0u,m0v,o));
        m1v = fmaxf(m1v, __shfl_xor_sync(~0u,m1v,o));
    }
    a00 = __expf(a00-m0v); a01 = __expf(a01-m0v);
    a10 = __expf(a10-m1v); a11 = __expf(a11-m1v);
    float s0 = a00+a01, s1 = a10+a11;
#pragma unroll
    for (int o=16;o;o>>=1){
        s0 += __shfl_xor_sync(~0u,s0,o);
        s1 += __shfl_xor_sync(~0u,s1,o);
    }
    float i0 = 1.0f/s0, i1 = 1.0f/s1;
    *(float2*)(g_A1 + (size_t)row0*C1C + 2*l)       = make_float2(a00*i0, a01*i0);
    *(float2*)(g_A1 + (size_t)(row0+1)*C1C + 2*l)   = make_float2(a10*i1, a11*i1);
}

// ---- k4: f1 = A1^T @ f0 per graph ----
__global__ __launch_bounds__(256) void k4_pool1(){
    __shared__ float As[32][64];
    __shared__ float Fs[32][128];
    const int g = blockIdx.y, n0 = blockIdx.x*128;
    const int tid = threadIdx.x, tx = tid&15, ty = tid>>4;
    float acc[4][8];
#pragma unroll
    for (int i=0;i<4;i++)
#pragma unroll
        for (int j=0;j<8;j++) acc[i][j]=0.f;
    const float* A1p = g_A1 + (size_t)g*C0C*C1C;
    const float* f0p = g_f0 + (size_t)g*C0C*HD;
    for (int kb=0;kb<C0C;kb+=32){
#pragma unroll
        for (int i=0;i<2;i++){
            int idx = tid + i*256;
            *(float4*)&As[idx>>4][(idx&15)*4] = *(const float4*)(A1p + (size_t)(kb+(idx>>4))*C1C + (idx&15)*4);
        }
#pragma unroll
        for (int i=0;i<4;i++){
            int idx = tid + i*256;
            *(float4*)&Fs[idx>>5][(idx&31)*4] = *(const float4*)(f0p + (size_t)(kb+(idx>>5))*HD + n0 + (idx&31)*4);
        }
        __syncthreads();
#pragma unroll
        for (int k=0;k<32;k++){
            float a[4], b[8];
            *(float4*)&a[0] = *(float4*)&As[k][ty*4];
            *(float4*)&b[0] = *(float4*)&Fs[k][tx*4];
            *(float4*)&b[4] = *(float4*)&Fs[k][tx*4+64];
#pragma unroll
            for (int i=0;i<4;i++)
#pragma unroll
                for (int j=0;j<8;j++) acc[i][j] = fmaf(a[i], b[j], acc[i][j]);
        }
        __syncthreads();
    }
    float* f1p = g_f1 + (size_t)g*C1C*HD;
#pragma unroll
    for (int ii=0;ii<4;ii++)
#pragma unroll
        for (int gn=0;gn<2;gn++)
            *(float4*)(f1p + (size_t)(ty*4+ii)*HD + n0 + tx*4 + gn*64) =
                make_float4(acc[ii][gn*4],acc[ii][gn*4+1],acc[ii][gn*4+2],acc[ii][gn*4+3]);
}

// ---- k5: K-split final GEMM partials ----
__global__ __launch_bounds__(256) void k5_final_part(const float* __restrict__ Wf){
    __shared__ float Fs[64][33];
    __shared__ float Ws[32][32];
    const int n0 = blockIdx.x*32, ks = blockIdx.y;
    const int tid = threadIdx.x, tx = tid&31, ty = tid>>5;
    float acc[8];
#pragma unroll
    for (int i=0;i<8;i++) acc[i]=0.f;
    const int kbeg = ks*1024;
    for (int kb=kbeg; kb<kbeg+1024; kb+=32){
#pragma unroll
        for (int i=0;i<2;i++){
            int idx = tid + i*256;
            int m = idx>>3, k = (idx&7)*4;
            float4 v = *(const float4*)(g_f1 + (size_t)m*(C1C*HD) + kb + k);
            Fs[m][k]=v.x; Fs[m][k+1]=v.y; Fs[m][k+2]=v.z; Fs[m][k+3]=v.w;
        }
        *(float4*)&Ws[tid>>3][(tid&7)*4] = *(const float4*)(Wf + (size_t)(kb+(tid>>3))*HD + n0 + (tid&7)*4);
        __syncthreads();
#pragma unroll
        for (int kk=0;kk<32;kk++){
            float b = Ws[kk][tx];
#pragma unroll
            for (int i=0;i<8;i++) acc[i] = fmaf(Fs[ty*8+i][kk], b, acc[i]);
        }
        __syncthreads();
    }
#pragma unroll
    for (int i=0;i<8;i++)
        g_part[(size_t)(ks*BG + ty*8+i)*HD + n0 + tx] = acc[i];
}

// ---- k6: reduce + bias + relu ----
__global__ __launch_bounds__(256) void k6_reduce(const float* __restrict__ bf, float* __restrict__ out){
    int idx = blockIdx.x*256 + threadIdx.x;
    float s = __ldg(bf + (idx&255));
#pragma unroll
    for (int ks=0;ks<KSPLIT;ks++) s += g_part[(size_t)ks*(BG*HD) + idx];
    out[idx] = fmaxf(s, 0.f);
}

extern "C" void kernel_launch(void* const* d_in, const int* in_sizes, int n_in,
                              void* d_out, int out_size){
    const float* x  = (const float*)d_in[0];
    const float* W0 = (const float*)d_in[3];
    const float* b0 = (const float*)d_in[4];
    const float* W1 = (const float*)d_in[5];
    const float* b1 = (const float*)d_in[6];
    const float* Wf = (const float*)d_in[7];
    const float* bf = (const float*)d_in[8];
    float* out = (float*)d_out;

    cudaFuncSetAttribute(k1m, cudaFuncAttributeMaxDynamicSharedMemorySize, K1_SMEM);
    cudaFuncSetAttribute(k2m, cudaFuncAttributeMaxDynamicSharedMemorySize, K2_SMEM);
    cudaFuncSetAttribute(k3n, cudaFuncAttributeMaxDynamicSharedMemorySize, K3_SMEM);

    kW<<<C0C*HD/2/256, 256>>>(W0);
    k1m<<<NTOT/64, 256, K1_SMEM>>>(x, b0);
    kNop<<<1, 32>>>();                       // spacer -> ncu captures k2m (idx 3)
    k2m<<<dim3(4, 2, BG), 256, K2_SMEM>>>(x);
    k3n<<<BG*C0C/32, 512, K3_SMEM>>>(W1, b1);
    k4_pool1<<<dim3(2, BG), 256>>>();
    k5_final_part<<<dim3(8, KSPLIT), 256>>>(Wf);
    k6_reduce<<<BG*HD/256, 256>>>(bf, out);
}

// round 16
// speedup vs baseline: 1.1463x; 1.1463x over previous
#include <cuda_runtime.h>
#include <cuda_bf16.h>

#define HD 256
#define BG 64
#define NPGC 4096
#define C0C 256
#define C1C 64
#define NTOT (BG*NPGC)
#define KSPLIT 16

__device__ unsigned g_A0P[(size_t)BG*C0C*NPGC];  // packed bf16 hi|lo<<16, [g][c][n]
__device__ unsigned g_W0H[C0C*HD/2];             // W0^T hi pairs [c][128]
__device__ unsigned g_W0L[C0C*HD/2];
__device__ float g_f0[(size_t)BG*C0C*HD];
__device__ float g_A1[(size_t)BG*C0C*C1C];
__device__ float g_f1[(size_t)BG*C1C*HD];
__device__ float g_part[(size_t)KSPLIT*BG*HD];

__device__ __forceinline__ unsigned pack1(float v){
    __nv_bfloat16 h = __float2bfloat16(v);
    __nv_bfloat16 lo = __float2bfloat16(v - __bfloat162float(h));
    return (unsigned)__bfloat16_as_ushort(h) | ((unsigned)__bfloat16_as_ushort(lo)<<16);
}
__device__ __forceinline__ void split2(float a, float b, unsigned& hi, unsigned& lo){
    __nv_bfloat16 ha = __float2bfloat16(a), hb = __float2bfloat16(b);
    __nv_bfloat16 la = __float2bfloat16(a - __bfloat162float(ha));
    __nv_bfloat16 lb = __float2bfloat16(b - __bfloat162float(hb));
    hi = (unsigned)__bfloat16_as_ushort(ha) | ((unsigned)__bfloat16_as_ushort(hb)<<16);
    lo = (unsigned)__bfloat16_as_ushort(la) | ((unsigned)__bfloat16_as_ushort(lb)<<16);
}
__device__ __forceinline__ void mma16816(float* c, const unsigned* a, const unsigned* b){
    asm volatile("mma.sync.aligned.m16n8k16.row.col.f32.bf16.bf16.f32 "
        "{%0,%1,%2,%3}, {%4,%5,%6,%7}, {%8,%9}, {%0,%1,%2,%3};"
        : "+f"(c[0]),"+f"(c[1]),"+f"(c[2]),"+f"(c[3])
        : "r"(a[0]),"r"(a[1]),"r"(a[2]),"r"(a[3]), "r"(b[0]),"r"(b[1]));
}

// W0^T split into hi/lo pair arrays
__global__ void kW(const float* __restrict__ W0){
    int i = blockIdx.x*256 + threadIdx.x;    // 32768
    int c = i>>7, kp = i&127;
    unsigned hi, lo;
    split2(W0[(size_t)(2*kp)*C0C + c], W0[(size_t)(2*kp+1)*C0C + c], hi, lo);
    g_W0H[c*128+kp] = hi; g_W0L[c*128+kp] = lo;
}

// =========================================================================
// k1m: A0 = softmax(x@W0+b0). Tile M=64 x N=256, 2 CTAs/SM. (R14 exact)
// =========================================================================
#define K1_SMEM (23552*4)   // 94208
__global__ __launch_bounds__(256,2) void k1m(const float* __restrict__ x,
                                             const float* __restrict__ b0){
    extern __shared__ __align__(16) unsigned sm[];
    float* sums = (float*)sm;
    float* b0s  = (float*)(sm + 256);
    unsigned* sXh = sm + 512;                 // [64][36]
    unsigned* sXl = sm + 2816;
    unsigned* sWh = sm + 5120;                // [256][36]
    unsigned* sWl = sm + 14336;
    unsigned* buf = sm + 512;                 // epilogue staging [256][68]
    const int tid = threadIdx.x, l = tid&31, wid = tid>>5;
    const int wm = wid&1, wn = wid>>1;
    const int row0 = blockIdx.x*64;

    b0s[tid] = b0[tid];
    float acc[2][8][4];
#pragma unroll
    for(int t=0;t<2;t++)
#pragma unroll
        for(int j=0;j<8;j++)
#pragma unroll
            for(int q=0;q<4;q++) acc[t][j][q]=0.f;

    for(int kc=0;kc<4;kc++){
#pragma unroll
        for(int i=0;i<4;i++){
            int idx = tid + i*256, r = idx>>4, q = idx&15;
            float4 v = *(const float4*)(x + (size_t)(row0+r)*HD + kc*64 + q*4);
            unsigned h0,l0,h1,l1;
            split2(v.x, v.y, h0, l0); split2(v.z, v.w, h1, l1);
            *(uint2*)(sXh + r*36 + q*2) = make_uint2(h0,h1);
            *(uint2*)(sXl + r*36 + q*2) = make_uint2(l0,l1);
        }
#pragma unroll
        for(int i=0;i<8;i++){
            int idx = tid + i*256, c = idx>>3, q = (idx&7)*4;
            *(uint4*)(sWh + c*36 + q) = *(const uint4*)(g_W0H + c*128 + kc*32 + q);
            *(uint4*)(sWl + c*36 + q) = *(const uint4*)(g_W0L + c*128 + kc*32 + q);
        }
        __syncthreads();
        for(int k16=0;k16<4;k16++){
            int kp = k16*8;
            unsigned ah[2][4], al[2][4];
#pragma unroll
            for(int t=0;t<2;t++){
                int ra = (wm*32 + t*16 + (l>>2))*36 + kp + (l&3);
                ah[t][0]=sXh[ra];       ah[t][1]=sXh[ra+8*36];
                ah[t][2]=sXh[ra+4];     ah[t][3]=sXh[ra+8*36+4];
                al[t][0]=sXl[ra];       al[t][1]=sXl[ra+8*36];
                al[t][2]=sXl[ra+4];     al[t][3]=sXl[ra+8*36+4];
            }
#pragma unroll
            for(int j=0;j<8;j++){
                int rb = (wn*64 + j*8 + (l>>2))*36 + kp + (l&3);
                unsigned bh[2], bl[2];
                bh[0]=sWh[rb]; bh[1]=sWh[rb+4];
                bl[0]=sWl[rb]; bl[1]=sWl[rb+4];
#pragma unroll
                for(int t=0;t<2;t++){
                    mma16816(acc[t][j], ah[t], bh);
                    mma16816(acc[t][j], ah[t], bl);
                    mma16816(acc[t][j], al[t], bh);
                }
            }
        }
        __syncthreads();
    }

    float rs[2][2] = {{0.f,0.f},{0.f,0.f}};
#pragma unroll
    for(int t=0;t<2;t++)
#pragma unroll
        for(int j=0;j<8;j++){
            int col = wn*64 + j*8 + (l&3)*2;
            float e0=__expf(acc[t][j][0]+b0s[col]),   e1=__expf(acc[t][j][1]+b0s[col+1]);
            float e2=__expf(acc[t][j][2]+b0s[col]),   e3=__expf(acc[t][j][3]+b0s[col+1]);
            acc[t][j][0]=e0; acc[t][j][1]=e1; acc[t][j][2]=e2; acc[t][j][3]=e3;
            rs[t][0]+=e0+e1; rs[t][1]+=e2+e3;
        }
#pragma unroll
    for(int t=0;t<2;t++)
#pragma unroll
        for(int h=0;h<2;h++){
            float s = rs[t][h];
            s += __shfl_xor_sync(~0u,s,1); s += __shfl_xor_sync(~0u,s,2);
            rs[t][h]=s;
        }
    if((l&3)==0){
#pragma unroll
        for(int t=0;t<2;t++)
#pragma unroll
            for(int h=0;h<2;h++)
                sums[(wm*32+t*16+(l>>2)+8*h)*4 + wn] = rs[t][h];
    }
    __syncthreads();
    float inv[2][2];
#pragma unroll
    for(int t=0;t<2;t++)
#pragma unroll
        for(int h=0;h<2;h++){
            int r = wm*32+t*16+(l>>2)+8*h;
            inv[t][h] = 1.0f/(sums[r*4]+sums[r*4+1]+sums[r*4+2]+sums[r*4+3]);
        }
#pragma unroll
    for(int t=0;t<2;t++)
#pragma unroll
        for(int j=0;j<8;j++){
            int col = wn*64 + j*8 + (l&3)*2;
            int r0 = wm*32 + t*16 + (l>>2), r1 = r0+8;
            buf[col*68 + r0]     = pack1(acc[t][j][0]*inv[t][0]);
            buf[(col+1)*68 + r0] = pack1(acc[t][j][1]*inv[t][0]);
            buf[col*68 + r1]     = pack1(acc[t][j][2]*inv[t][1]);
            buf[(col+1)*68 + r1] = pack1(acc[t][j][3]*inv[t][1]);
        }
    __syncthreads();
    const int g = row0>>12, nl0 = row0&4095;
#pragma unroll
    for(int cc=0;cc<16;cc++){
        int c = wid*32 + cc*2 + (l>>4);
        uint4 v = *(uint4*)(buf + c*68 + (l&15)*4);
        *(uint4*)(g_A0P + ((size_t)g*C0C + c)*NPGC + nl0 + (l&15)*4) = v;
    }
}

// =========================================================================
// k2m: f0 = A0^T @ x. Tile 128x128, 256 thr, 2 CTAs/SM. (R14/R12 exact)
// =========================================================================
#define K2_SMEM (26880*4)
__global__ __launch_bounds__(256,2) void k2m(const float* __restrict__ x){
    extern __shared__ __align__(16) unsigned sm[];
    unsigned* sAh = sm;
    unsigned* sAl = sm + 4608;
    unsigned* sBh = sm + 9216;
    unsigned* sBl = sm + 13824;
    float*    sF  = (float*)(sm + 18432);     // [64 n][132 h]
    const int tid = threadIdx.x, l = tid&31, wid = tid>>5;
    const int wm = wid&3, wn = wid>>2;
    const int m0 = blockIdx.x*128, n0 = blockIdx.y*128, g = blockIdx.z;
    const unsigned* Ap = g_A0P + (size_t)g*C0C*NPGC;
    const float* xp = x + (size_t)g*NPGC*HD;

    float acc[2][8][4];
#pragma unroll
    for(int t=0;t<2;t++)
#pragma unroll
        for(int j=0;j<8;j++)
#pragma unroll
            for(int q=0;q<4;q++) acc[t][j][q]=0.f;

    for(int kc=0;kc<64;kc++){
#pragma unroll
        for(int i=0;i<8;i++){
            int idx = tid + i*256, r = idx>>4, q = idx&15;
            uint4 w = *(const uint4*)(Ap + (size_t)(m0+r)*NPGC + kc*64 + q*4);
            unsigned h01 = __byte_perm(w.x,w.y,0x5410), h23 = __byte_perm(w.z,w.w,0x5410);
            unsigned l01 = __byte_perm(w.x,w.y,0x7632), l23 = __byte_perm(w.z,w.w,0x7632);
            *(uint2*)(sAh + r*36 + q*2) = make_uint2(h01,h23);
            *(uint2*)(sAl + r*36 + q*2) = make_uint2(l01,l23);
        }
#pragma unroll
        for(int i=0;i<8;i++){
            int idx = tid + i*256, n = idx>>5, h4 = idx&31;
            *(float4*)(sF + n*132 + h4*4) =
                *(const float4*)(xp + (size_t)(kc*64+n)*HD + n0 + h4*4);
        }
        __syncthreads();
        {
            int h = tid & 127;
            int n4b = (tid >> 7) * 8;
#pragma unroll
            for(int n4=0;n4<8;n4++){
                int nn = n4b + n4;
                float f0v = sF[(nn*4+0)*132 + h], f1v = sF[(nn*4+1)*132 + h];
                float f2v = sF[(nn*4+2)*132 + h], f3v = sF[(nn*4+3)*132 + h];
                unsigned h0,l0,h1,l1;
                split2(f0v, f1v, h0, l0); split2(f2v, f3v, h1, l1);
                *(uint2*)(sBh + h*36 + nn*2) = make_uint2(h0,h1);
                *(uint2*)(sBl + h*36 + nn*2) = make_uint2(l0,l1);
            }
        }
        __syncthreads();
        for(int k16=0;k16<4;k16++){
            int kp = k16*8;
            unsigned ah[2][4], al[2][4];
#pragma unroll
            for(int t=0;t<2;t++){
                int ra = (wm*32 + t*16 + (l>>2))*36 + kp + (l&3);
                ah[t][0]=sAh[ra];       ah[t][1]=sAh[ra+8*36];
                ah[t][2]=sAh[ra+4];     ah[t][3]=sAh[ra+8*36+4];
                al[t][0]=sAl[ra];       al[t][1]=sAl[ra+8*36];
                al[t][2]=sAl[ra+4];     al[t][3]=sAl[ra+8*36+4];
            }
#pragma unroll
            for(int j=0;j<8;j++){
                int rb = (wn*64 + j*8 + (l>>2))*36 + kp + (l&3);
                unsigned bh[2], bl[2];
                bh[0]=sBh[rb]; bh[1]=sBh[rb+4];
                bl[0]=sBl[rb]; bl[1]=sBl[rb+4];
#pragma unroll
                for(int t=0;t<2;t++){
                    mma16816(acc[t][j], ah[t], bh);
                    mma16816(acc[t][j], ah[t], bl);
                    mma16816(acc[t][j], al[t], bh);
                }
            }
        }
        __syncthreads();
    }
    float* f0p = g_f0 + ((size_t)g*C0C + m0)*HD + n0;
#pragma unroll
    for(int t=0;t<2;t++)
#pragma unroll
        for(int j=0;j<8;j++){
            int col = wn*64 + j*8 + (l&3)*2;
            int r0 = wm*32 + t*16 + (l>>2);
            *(float2*)(f0p + (size_t)r0*HD + col)     = make_float2(acc[t][j][0],acc[t][j][1]);
            *(float2*)(f0p + (size_t)(r0+8)*HD + col) = make_float2(acc[t][j][2],acc[t][j][3]);
        }
}

// ---- k3: A1 = softmax(f0 @ W1 + b1). 4 rows per warp, 64 rows/block ----
#define K3_SMEM ((16384 + 64*256)*4)   // 131072
__global__ __launch_bounds__(512) void k3n(const float* __restrict__ W1,
                                           const float* __restrict__ b1){
    extern __shared__ float s3[];
    float* sW = s3;                // [256][64]
    float* srow = s3 + 16384;      // [64][256]
    const int tid = threadIdx.x, l = tid&31, w = tid>>5;
#pragma unroll
    for(int i=0;i<8;i++){
        int idx = tid + i*512;
        *(float4*)(sW + idx*4) = *(const float4*)(W1 + idx*4);
    }
    const int row0 = blockIdx.x*64 + w*4;
    const float* xr0 = g_f0 + (size_t)row0*HD;
#pragma unroll
    for(int rr=0;rr<4;rr++){
        *(float4*)(srow + (w*4+rr)*256 + l*8)     = *(const float4*)(xr0 + rr*HD + l*8);
        *(float4*)(srow + (w*4+rr)*256 + l*8 + 4) = *(const float4*)(xr0 + rr*HD + l*8 + 4);
    }
    __syncthreads();
    float a[4][2];
#pragma unroll
    for(int rr=0;rr<4;rr++){ a[rr][0]=0.f; a[rr][1]=0.f; }
    const float* rw = srow + (size_t)w*4*256;
#pragma unroll 4
    for(int k=0;k<HD;k++){
        float2 wv = *(float2*)(sW + k*64 + 2*l);
#pragma unroll
        for(int rr=0;rr<4;rr++){
            float xv = rw[rr*256 + k];
            a[rr][0] = fmaf(xv, wv.x, a[rr][0]);
            a[rr][1] = fmaf(xv, wv.y, a[rr][1]);
        }
    }
    float2 bb = *(const float2*)(b1 + 2*l);
#pragma unroll
    for(int rr=0;rr<4;rr++){
        float a0 = a[rr][0] + bb.x, a1 = a[rr][1] + bb.y;
        float m = fmaxf(a0, a1);
#pragma unroll
        for(int o=16;o;o>>=1) m = fmaxf(m, __shfl_xor_sync(~0u,m,o));
        a0 = __expf(a0-m); a1 = __expf(a1-m);
        float s = a0+a1;
#pragma unroll
        for(int o=16;o;o>>=1) s += __shfl_xor_sync(~0u,s,o);
        float inv = 1.0f/s;
        *(float2*)(g_A1 + (size_t)(row0+rr)*C1C + 2*l) = make_float2(a0*inv, a1*inv);
    }
}

// ---- k4: f1 = A1^T @ f0 per graph. Tile 64m x 64n, grid (4, 64) ----
__global__ __launch_bounds__(256) void k4_pool1(){
    __shared__ float As[32][64];
    __shared__ float Fs[32][64];
    const int g = blockIdx.y, n0 = blockIdx.x*64;
    const int tid = threadIdx.x, tx = tid&15, ty = tid>>4;
    float acc[4][4];
#pragma unroll
    for (int i=0;i<4;i++)
#pragma unroll
        for (int j=0;j<4;j++) acc[i][j]=0.f;
    const float* A1p = g_A1 + (size_t)g*C0C*C1C;
    const float* f0p = g_f0 + (size_t)g*C0C*HD;
    for (int kb=0;kb<C0C;kb+=32){
#pragma unroll
        for (int i=0;i<2;i++){
            int idx = tid + i*256;
            *(float4*)&As[idx>>4][(idx&15)*4] = *(const float4*)(A1p + (size_t)(kb+(idx>>4))*C1C + (idx&15)*4);
        }
#pragma unroll
        for (int i=0;i<2;i++){
            int idx = tid + i*256;
            *(float4*)&Fs[idx>>4][(idx&15)*4] = *(const float4*)(f0p + (size_t)(kb+(idx>>4))*HD + n0 + (idx&15)*4);
        }
        __syncthreads();
#pragma unroll
        for (int k=0;k<32;k++){
            float a[4], b[4];
            *(float4*)&a[0] = *(float4*)&As[k][ty*4];
            *(float4*)&b[0] = *(float4*)&Fs[k][tx*4];
#pragma unroll
            for (int i=0;i<4;i++)
#pragma unroll
                for (int j=0;j<4;j++) acc[i][j] = fmaf(a[i], b[j], acc[i][j]);
        }
        __syncthreads();
    }
    float* f1p = g_f1 + (size_t)g*C1C*HD;
#pragma unroll
    for (int ii=0;ii<4;ii++)
        *(float4*)(f1p + (size_t)(ty*4+ii)*HD + n0 + tx*4) =
            make_float4(acc[ii][0],acc[ii][1],acc[ii][2],acc[ii][3]);
}

// ---- k5: K-split final GEMM partials ----
__global__ __launch_bounds__(256) void k5_final_part(const float* __restrict__ Wf){
    __shared__ float Fs[64][33];
    __shared__ float Ws[32][32];
    const int n0 = blockIdx.x*32, ks = blockIdx.y;
    const int tid = threadIdx.x, tx = tid&31, ty = tid>>5;
    float acc[8];
#pragma unroll
    for (int i=0;i<8;i++) acc[i]=0.f;
    const int kbeg = ks*1024;
    for (int kb=kbeg; kb<kbeg+1024; kb+=32){
#pragma unroll
        for (int i=0;i<2;i++){
            int idx = tid + i*256;
            int m = idx>>3, k = (idx&7)*4;
            float4 v = *(const float4*)(g_f1 + (size_t)m*(C1C*HD) + kb + k);
            Fs[m][k]=v.x; Fs[m][k+1]=v.y; Fs[m][k+2]=v.z; Fs[m][k+3]=v.w;
        }
        *(float4*)&Ws[tid>>3][(tid&7)*4] = *(const float4*)(Wf + (size_t)(kb+(tid>>3))*HD + n0 + (tid&7)*4);
        __syncthreads();
#pragma unroll
        for (int kk=0;kk<32;kk++){
            float b = Ws[kk][tx];
#pragma unroll
            for (int i=0;i<8;i++) acc[i] = fmaf(Fs[ty*8+i][kk], b, acc[i]);
        }
        __syncthreads();
    }
#pragma unroll
    for (int i=0;i<8;i++)
        g_part[(size_t)(ks*BG + ty*8+i)*HD + n0 + tx] = acc[i];
}

// ---- k6: reduce + bias + relu ----
__global__ __launch_bounds__(256) void k6_reduce(const float* __restrict__ bf, float* __restrict__ out){
    int idx = blockIdx.x*256 + threadIdx.x;
    float s = __ldg(bf + (idx&255));
#pragma unroll
    for (int ks=0;ks<KSPLIT;ks++) s += g_part[(size_t)ks*(BG*HD) + idx];
    out[idx] = fmaxf(s, 0.f);
}

extern "C" void kernel_launch(void* const* d_in, const int* in_sizes, int n_in,
                              void* d_out, int out_size){
    const float* x  = (const float*)d_in[0];
    const float* W0 = (const float*)d_in[3];
    const float* b0 = (const float*)d_in[4];
    const float* W1 = (const float*)d_in[5];
    const float* b1 = (const float*)d_in[6];
    const float* Wf = (const float*)d_in[7];
    const float* bf = (const float*)d_in[8];
    float* out = (float*)d_out;

    cudaFuncSetAttribute(k1m, cudaFuncAttributeMaxDynamicSharedMemorySize, K1_SMEM);
    cudaFuncSetAttribute(k2m, cudaFuncAttributeMaxDynamicSharedMemorySize, K2_SMEM);
    cudaFuncSetAttribute(k3n, cudaFuncAttributeMaxDynamicSharedMemorySize, K3_SMEM);

    kW<<<C0C*HD/2/256, 256>>>(W0);
    k1m<<<NTOT/64, 256, K1_SMEM>>>(x, b0);
    k2m<<<dim3(2, 2, BG), 256, K2_SMEM>>>(x);
    k3n<<<BG*C0C/64, 512, K3_SMEM>>>(W1, b1);   // ncu captures this (4th launch)
    k4_pool1<<<dim3(4, BG), 256>>>();
    k5_final_part<<<dim3(8, KSPLIT), 256>>>(Wf);
    k6_reduce<<<BG*HD/256, 256>>>(bf, out);
}